// round 7
// baseline (speedup 1.0000x reference)
#include <cuda_runtime.h>
#include <cuda_fp16.h>

#define B    4
#define LQ   512
#define LK   512
#define E    128
#define D    256
#define TL   8            // l-rows per score/context CTA
#define QT   32           // qq per stage tile
#define QBLK 128          // qq per score-CTA
#define NTA  (QBLK / QT)  // 4 tiles per score-CTA
#define NTHR 256

// Scratch (allocation-free rule: __device__ globals)
__device__ float g_qproj[B * LQ * E];
__device__ float g_kproj[B * LK * E];
__device__ float g_scores[B * LK * LQ];   // raw scores (pre-softmax)

__device__ __forceinline__ __half2 tanh_h2(__half2 x) {
    unsigned xu = *reinterpret_cast<unsigned*>(&x);
    unsigned r;
    asm("tanh.approx.f16x2 %0, %1;" : "=r"(r) : "r"(xu));
    return *reinterpret_cast<__half2*>(&r);
}
__device__ __forceinline__ void cpasync16(void* smem_dst, const void* gsrc) {
    unsigned s = (unsigned)__cvta_generic_to_shared(smem_dst);
    asm volatile("cp.async.cg.shared.global [%0], [%1], 16;" :: "r"(s), "l"(gsrc));
}

// ---------------------------------------------------------------------------
// Projection: out[r][e] = sum_d X[r][d] * W[d][e]. 16 rows per CTA so W is
// read 128x fewer times than row count (33MB L2 total vs 134MB before).
// Grid (B*L/16 = 128, 2), 256 thr. thread = (ep = e-pair, rg = row group).
// ---------------------------------------------------------------------------
__global__ __launch_bounds__(NTHR) void proj_kernel(
    const float* __restrict__ query, const float* __restrict__ key,
    const float* __restrict__ Wc1,   const float* __restrict__ Wc2)
{
    const float* X; const float* W; float* O;
    if (blockIdx.y == 0) { X = query; W = Wc1; O = g_qproj; }
    else                 { X = key;   W = Wc2; O = g_kproj; }

    const int row0 = blockIdx.x * 16;
    const int tid  = threadIdx.x;
    const int ep   = tid & 63;           // e-pair 0..63 (E/2)
    const int rg   = tid >> 6;           // 0..3 -> rows rg*4 .. rg*4+3

    __shared__ float xs[16 * D];         // 16 KB
    const float4* xv = (const float4*)(X + (size_t)row0 * D);
    #pragma unroll
    for (int i = tid; i < 16 * D / 4; i += NTHR)
        ((float4*)xs)[i] = xv[i];
    __syncthreads();

    const float2* Wp = (const float2*)W;  // [D][E/2]
    float2 a0 = make_float2(0.f, 0.f), a1 = a0, a2 = a0, a3 = a0;
    #pragma unroll 8
    for (int d = 0; d < D; d++) {
        float2 w = Wp[d * (E / 2) + ep];  // coalesced 512B/warp-quarter
        float x0 = xs[(rg * 4 + 0) * D + d];   // broadcast LDS
        float x1 = xs[(rg * 4 + 1) * D + d];
        float x2 = xs[(rg * 4 + 2) * D + d];
        float x3 = xs[(rg * 4 + 3) * D + d];
        a0.x += x0 * w.x; a0.y += x0 * w.y;
        a1.x += x1 * w.x; a1.y += x1 * w.y;
        a2.x += x2 * w.x; a2.y += x2 * w.y;
        a3.x += x3 * w.x; a3.y += x3 * w.y;
    }
    float2* Op = (float2*)O;
    Op[(size_t)(row0 + rg * 4 + 0) * (E / 2) + ep] = a0;
    Op[(size_t)(row0 + rg * 4 + 1) * (E / 2) + ep] = a1;
    Op[(size_t)(row0 + rg * 4 + 2) * (E / 2) + ep] = a2;
    Op[(size_t)(row0 + rg * 4 + 3) * (E / 2) + ep] = a3;
}

// ---------------------------------------------------------------------------
// Score kernel: raw scores -> g_scores.
// Grid (LQ/QBLK=4, LK/TL=64, B=4) = 1024 CTAs, 256 thr, occ target 7.
// Single qs buffer (cp.async; cross-CTA overlap hides the wait at occ 7).
// lane = (lrow = lane>>2, qoff = lane&3); warp w owns qq = w*4+qoff per tile.
// ---------------------------------------------------------------------------
__global__ __launch_bounds__(NTHR, 7) void score_kernel(
    const float* __restrict__ vc, float* __restrict__ sc_out)
{
    const int qblk = blockIdx.x;
    const int l0   = blockIdx.y * TL;
    const int b    = blockIdx.z;
    const int tid  = threadIdx.x;
    const int w    = tid >> 5;
    const int lane = tid & 31;

    __shared__ float   ks[TL][132];      // 4.2 KB padded
    __shared__ __half2 vcs[E / 2];       // 256 B
    __shared__ float   qs[QT][132];      // 16.9 KB single buffer, padded

    for (int i = tid; i < TL * E; i += NTHR)
        ks[i >> 7][i & 127] = g_kproj[(size_t)(b * LK + l0 + (i >> 7)) * E + (i & 127)];
    if (tid < E / 2)
        vcs[tid] = __floats2half2_rn(vc[2 * tid], vc[2 * tid + 1]);

    const float4* qbase = (const float4*)(g_qproj + ((size_t)b * LQ + qblk * QBLK) * E);

    const int lrow = lane >> 2;              // 0..7
    const int qrow = w * 4 + (lane & 3);     // 0..31 within tile
    float* orow = sc_out + (size_t)(b * LK + l0 + lrow) * LQ + qblk * QBLK + qrow;

    #pragma unroll 1
    for (int t = 0; t < NTA; t++) {
        __syncthreads();                     // qs free (covers ks/vcs at t=0)
        const float4* src = qbase + t * (QT * E / 4);
        #pragma unroll
        for (int j = 0; j < 4; j++) {
            int i = tid + j * NTHR;          // 0..1023 float4s
            cpasync16(&qs[i >> 5][(i & 31) * 4], src + i);
        }
        asm volatile("cp.async.commit_group;");
        asm volatile("cp.async.wait_group 0;");
        __syncthreads();                     // qs visible

        const float4* qp = (const float4*)qs[qrow];
        const float4* kp = (const float4*)ks[lrow];
        const uint2*  vp = (const uint2*)vcs;

        float facc = 0.f;
        #pragma unroll 4
        for (int c = 0; c < E / 16; c++) {               // 8 chunks of 16 e
            __half2 acc01 = __float2half2_rn(0.f);
            __half2 acc23 = __float2half2_rn(0.f);
            #pragma unroll
            for (int u = 0; u < 4; u++) {
                const int e4 = c * 4 + u;
                float4 q = qp[e4];                       // 1 phase (8-way dup)
                float4 k = kp[e4];                       // 1 phase (4-way dup)
                uint2  v = vp[e4];                       // broadcast
                __half2 h01 = __floats2half2_rn(q.x + k.x, q.y + k.y);
                __half2 h23 = __floats2half2_rn(q.z + k.z, q.w + k.w);
                __half2 t01 = tanh_h2(h01);
                __half2 t23 = tanh_h2(h23);
                __half2 v01 = *reinterpret_cast<__half2*>(&v.x);
                __half2 v23 = *reinterpret_cast<__half2*>(&v.y);
                acc01 = __hfma2(v01, t01, acc01);
                acc23 = __hfma2(v23, t23, acc23);
            }
            float2 f01 = __half22float2(acc01);
            float2 f23 = __half22float2(acc23);
            facc += (f01.x + f01.y) + (f23.x + f23.y);
        }
        orow[t * QT] = facc;                              // raw score
    }
}

// ---------------------------------------------------------------------------
// Fused softmax + context. Grid (2 D-halves, LK/TL=64, B) = 512 CTAs, 256 thr.
// Softmax: warp w owns row l0+w (reads raw g_scores, writes probs to ps and,
// for dsl==0, to att_out). GEMM: thread = (d4g = lane -> float4 col within
// D-half, qg = warp -> 64-qq block); 8 l-row accumulators per thread;
// 8-way partial reduction through smem.
// ---------------------------------------------------------------------------
__global__ __launch_bounds__(NTHR, 4) void context_kernel(
    const float* __restrict__ value, const float* __restrict__ scores,
    float* __restrict__ att_out, float* __restrict__ ctx_out)
{
    const int dsl = blockIdx.x;              // 0..1 : D-half
    const int l0  = blockIdx.y * TL;
    const int b   = blockIdx.z;
    const int tid = threadIdx.x;
    const int w   = tid >> 5;                // warp = l-row (softmax) = qq block (gemm)
    const int lane = tid & 31;

    __shared__ float  ps[TL][LQ];            // 16 KB probabilities
    __shared__ float4 red[TL][TL][32];       // 32 KB partials [qg][l][d4g]

    // ---- softmax (warp w owns row l0 + w) ----
    {
        const float4* srow = (const float4*)(scores + (size_t)(b * LK + l0 + w) * LQ);
        float4 v[4];
        float m = -1e30f;
        #pragma unroll
        for (int k = 0; k < 4; k++) {
            v[k] = srow[lane + 32 * k];
            m = fmaxf(m, fmaxf(fmaxf(v[k].x, v[k].y), fmaxf(v[k].z, v[k].w)));
        }
        #pragma unroll
        for (int o = 16; o; o >>= 1) m = fmaxf(m, __shfl_xor_sync(0xffffffffu, m, o));
        float s = 0.f;
        #pragma unroll
        for (int k = 0; k < 4; k++) {
            v[k].x = __expf(v[k].x - m); v[k].y = __expf(v[k].y - m);
            v[k].z = __expf(v[k].z - m); v[k].w = __expf(v[k].w - m);
            s += (v[k].x + v[k].y) + (v[k].z + v[k].w);
        }
        #pragma unroll
        for (int o = 16; o; o >>= 1) s += __shfl_xor_sync(0xffffffffu, s, o);
        const float inv = __fdividef(1.f, s);

        float4* prow = (float4*)ps[w];
        float4* arow = (float4*)(att_out + (size_t)(b * LK + l0 + w) * LQ);
        #pragma unroll
        for (int k = 0; k < 4; k++) {
            v[k].x *= inv; v[k].y *= inv; v[k].z *= inv; v[k].w *= inv;
            prow[lane + 32 * k] = v[k];          // conflict-free STS.128
            if (dsl == 0) arow[lane + 32 * k] = v[k];
        }
    }
    __syncthreads();

    // ---- context GEMM: D-half dsl, qq block w ----
    const float4* vbase = (const float4*)(value + (size_t)b * LQ * D) + dsl * 32 + lane;

    float4 acc[TL];
    #pragma unroll
    for (int l = 0; l < TL; l++) acc[l] = make_float4(0.f, 0.f, 0.f, 0.f);

    const int q0 = w * 64;
    #pragma unroll 2
    for (int qc = 0; qc < 64; qc += 4) {
        const int qq = q0 + qc;
        float4 v0 = vbase[(qq + 0) * (D / 4)];
        float4 v1 = vbase[(qq + 1) * (D / 4)];
        float4 v2 = vbase[(qq + 2) * (D / 4)];
        float4 v3 = vbase[(qq + 3) * (D / 4)];
        #pragma unroll
        for (int l = 0; l < TL; l++) {
            float4 p = *(const float4*)&ps[l][qq];   // broadcast LDS.128
            acc[l].x += p.x * v0.x; acc[l].y += p.x * v0.y;
            acc[l].z += p.x * v0.z; acc[l].w += p.x * v0.w;
            acc[l].x += p.y * v1.x; acc[l].y += p.y * v1.y;
            acc[l].z += p.y * v1.z; acc[l].w += p.y * v1.w;
            acc[l].x += p.z * v2.x; acc[l].y += p.z * v2.y;
            acc[l].z += p.z * v2.z; acc[l].w += p.z * v2.w;
            acc[l].x += p.w * v3.x; acc[l].y += p.w * v3.y;
            acc[l].z += p.w * v3.z; acc[l].w += p.w * v3.w;
        }
    }

    #pragma unroll
    for (int l = 0; l < TL; l++)
        red[w][l][lane] = acc[l];
    __syncthreads();

    // thread (lane, w) reduces 8 partials for l-row w, its d4 column
    float4 c = make_float4(0.f, 0.f, 0.f, 0.f);
    #pragma unroll
    for (int g = 0; g < TL; g++) {
        float4 r = red[g][w][lane];
        c.x += r.x; c.y += r.y; c.z += r.z; c.w += r.w;
    }
    ((float4*)ctx_out)[(size_t)(b * LK + l0 + w) * (D / 4) + dsl * 32 + lane] = c;
}

// ---------------------------------------------------------------------------
extern "C" void kernel_launch(void* const* d_in, const int* in_sizes, int n_in,
                              void* d_out, int out_size)
{
    const float* query = (const float*)d_in[0];
    const float* key   = (const float*)d_in[1];
    const float* value = (const float*)d_in[2];
    const float* Wc1   = (const float*)d_in[3];
    const float* Wc2   = (const float*)d_in[4];
    const float* vc    = (const float*)d_in[5];

    float* ctx = (float*)d_out;                 // [B, LK, D]
    float* att = ctx + (size_t)B * LK * D;      // [B, LK, LQ]

    float* sc;
    cudaGetSymbolAddress((void**)&sc, g_scores);

    proj_kernel<<<dim3(B * LQ / 16, 2), NTHR>>>(query, key, Wc1, Wc2);
    score_kernel<<<dim3(LQ / QBLK, LK / TL, B), NTHR>>>(vc, sc);
    context_kernel<<<dim3(2, LK / TL, B), NTHR>>>(value, sc, att, ctx);
}

// round 8
// speedup vs baseline: 1.0611x; 1.0611x over previous
#include <cuda_runtime.h>
#include <cuda_fp16.h>

#define B    4
#define LQ   512
#define LK   512
#define E    128
#define D    256
#define TL   8            // l-rows per score/context CTA
#define QT   32           // qq per stage tile
#define QBLK 128          // qq per score-CTA
#define NTA  (QBLK / QT)  // 4 tiles per score-CTA
#define NTHR 256

// Scratch (allocation-free rule: __device__ globals)
__device__ float g_qproj[B * LQ * E];
__device__ float g_kproj[B * LK * E];
__device__ float g_scores[B * LK * LQ];   // raw scores (pre-softmax)

__device__ __forceinline__ __half2 tanh_h2(__half2 x) {
    unsigned xu = *reinterpret_cast<unsigned*>(&x);
    unsigned r;
    asm("tanh.approx.f16x2 %0, %1;" : "=r"(r) : "r"(xu));
    return *reinterpret_cast<__half2*>(&r);
}
__device__ __forceinline__ void cpasync16(void* smem_dst, const void* gsrc) {
    unsigned s = (unsigned)__cvta_generic_to_shared(smem_dst);
    asm volatile("cp.async.cg.shared.global [%0], [%1], 16;" :: "r"(s), "l"(gsrc));
}

// ---------------------------------------------------------------------------
// Projection: out[r][e] = sum_d X[r][d] * W[d][e].
// 16 rows/CTA (W L2 traffic 33MB total) BUT with latency fixed:
// 512 threads, thread = (ep = e-pair 0..63, rg = 0..7 -> rows 2rg, 2rg+1),
// W loads batched 8-deep (MLP 8) so L2/DRAM latency is overlapped.
// Grid (B*L/16 = 128, 2) = 256 CTAs x 512 thr.
// ---------------------------------------------------------------------------
__global__ __launch_bounds__(512) void proj_kernel(
    const float* __restrict__ query, const float* __restrict__ key,
    const float* __restrict__ Wc1,   const float* __restrict__ Wc2)
{
    const float* X; const float* W; float* O;
    if (blockIdx.y == 0) { X = query; W = Wc1; O = g_qproj; }
    else                 { X = key;   W = Wc2; O = g_kproj; }

    const int row0 = blockIdx.x * 16;
    const int tid  = threadIdx.x;
    const int ep   = tid & 63;           // e-pair 0..63 (E/2)
    const int rg   = tid >> 6;           // 0..7 -> rows 2rg, 2rg+1

    __shared__ float xs[16 * D];         // 16 KB
    const float4* xv = (const float4*)(X + (size_t)row0 * D);
    #pragma unroll
    for (int i = tid; i < 16 * D / 4; i += 512)
        ((float4*)xs)[i] = xv[i];
    __syncthreads();

    const float2* Wp = (const float2*)W;           // [D][E/2]
    const float*  x0s = xs + (2 * rg + 0) * D;
    const float*  x1s = xs + (2 * rg + 1) * D;

    float2 a0 = make_float2(0.f, 0.f), a1 = a0;
    #pragma unroll 1
    for (int d0 = 0; d0 < D; d0 += 8) {
        float2 w[8];
        #pragma unroll
        for (int j = 0; j < 8; j++)                // 8 independent LDG.64 (MLP 8)
            w[j] = Wp[(d0 + j) * (E / 2) + ep];
        #pragma unroll
        for (int j = 0; j < 8; j++) {
            float x0 = x0s[d0 + j];                // warp-uniform LDS broadcast
            float x1 = x1s[d0 + j];
            a0.x += x0 * w[j].x; a0.y += x0 * w[j].y;
            a1.x += x1 * w[j].x; a1.y += x1 * w[j].y;
        }
    }
    float2* Op = (float2*)O;
    Op[(size_t)(row0 + 2 * rg + 0) * (E / 2) + ep] = a0;
    Op[(size_t)(row0 + 2 * rg + 1) * (E / 2) + ep] = a1;
}

// ---------------------------------------------------------------------------
// Score kernel: raw scores -> g_scores.
// Grid (LQ/QBLK=4, LK/TL=64, B=4) = 1024 CTAs, 256 thr, occ target 7.
// (unchanged from R7 — part of the measured win)
// ---------------------------------------------------------------------------
__global__ __launch_bounds__(NTHR, 7) void score_kernel(
    const float* __restrict__ vc, float* __restrict__ sc_out)
{
    const int qblk = blockIdx.x;
    const int l0   = blockIdx.y * TL;
    const int b    = blockIdx.z;
    const int tid  = threadIdx.x;
    const int w    = tid >> 5;
    const int lane = tid & 31;

    __shared__ float   ks[TL][132];      // 4.2 KB padded
    __shared__ __half2 vcs[E / 2];       // 256 B
    __shared__ float   qs[QT][132];      // 16.9 KB single buffer, padded

    for (int i = tid; i < TL * E; i += NTHR)
        ks[i >> 7][i & 127] = g_kproj[(size_t)(b * LK + l0 + (i >> 7)) * E + (i & 127)];
    if (tid < E / 2)
        vcs[tid] = __floats2half2_rn(vc[2 * tid], vc[2 * tid + 1]);

    const float4* qbase = (const float4*)(g_qproj + ((size_t)b * LQ + qblk * QBLK) * E);

    const int lrow = lane >> 2;              // 0..7
    const int qrow = w * 4 + (lane & 3);     // 0..31 within tile
    float* orow = sc_out + (size_t)(b * LK + l0 + lrow) * LQ + qblk * QBLK + qrow;

    #pragma unroll 1
    for (int t = 0; t < NTA; t++) {
        __syncthreads();                     // qs free (covers ks/vcs at t=0)
        const float4* src = qbase + t * (QT * E / 4);
        #pragma unroll
        for (int j = 0; j < 4; j++) {
            int i = tid + j * NTHR;          // 0..1023 float4s
            cpasync16(&qs[i >> 5][(i & 31) * 4], src + i);
        }
        asm volatile("cp.async.commit_group;");
        asm volatile("cp.async.wait_group 0;");
        __syncthreads();                     // qs visible

        const float4* qp = (const float4*)qs[qrow];
        const float4* kp = (const float4*)ks[lrow];
        const uint2*  vp = (const uint2*)vcs;

        float facc = 0.f;
        #pragma unroll 4
        for (int c = 0; c < E / 16; c++) {               // 8 chunks of 16 e
            __half2 acc01 = __float2half2_rn(0.f);
            __half2 acc23 = __float2half2_rn(0.f);
            #pragma unroll
            for (int u = 0; u < 4; u++) {
                const int e4 = c * 4 + u;
                float4 q = qp[e4];                       // 1 phase (8-way dup)
                float4 k = kp[e4];                       // 1 phase (4-way dup)
                uint2  v = vp[e4];                       // broadcast
                __half2 h01 = __floats2half2_rn(q.x + k.x, q.y + k.y);
                __half2 h23 = __floats2half2_rn(q.z + k.z, q.w + k.w);
                __half2 t01 = tanh_h2(h01);
                __half2 t23 = tanh_h2(h23);
                __half2 v01 = *reinterpret_cast<__half2*>(&v.x);
                __half2 v23 = *reinterpret_cast<__half2*>(&v.y);
                acc01 = __hfma2(v01, t01, acc01);
                acc23 = __hfma2(v23, t23, acc23);
            }
            float2 f01 = __half22float2(acc01);
            float2 f23 = __half22float2(acc23);
            facc += (f01.x + f01.y) + (f23.x + f23.y);
        }
        orow[t * QT] = facc;                              // raw score
    }
}

// ---------------------------------------------------------------------------
// Fused softmax + context. Grid (2 D-halves, LK/TL=64, B) = 512 CTAs, 256 thr.
// (unchanged from R7 — part of the measured win)
// ---------------------------------------------------------------------------
__global__ __launch_bounds__(NTHR, 4) void context_kernel(
    const float* __restrict__ value, const float* __restrict__ scores,
    float* __restrict__ att_out, float* __restrict__ ctx_out)
{
    const int dsl = blockIdx.x;              // 0..1 : D-half
    const int l0  = blockIdx.y * TL;
    const int b   = blockIdx.z;
    const int tid = threadIdx.x;
    const int w   = tid >> 5;                // warp = l-row (softmax) = qq block (gemm)
    const int lane = tid & 31;

    __shared__ float  ps[TL][LQ];            // 16 KB probabilities
    __shared__ float4 red[TL][TL][32];       // 32 KB partials [qg][l][d4g]

    // ---- softmax (warp w owns row l0 + w) ----
    {
        const float4* srow = (const float4*)(scores + (size_t)(b * LK + l0 + w) * LQ);
        float4 v[4];
        float m = -1e30f;
        #pragma unroll
        for (int k = 0; k < 4; k++) {
            v[k] = srow[lane + 32 * k];
            m = fmaxf(m, fmaxf(fmaxf(v[k].x, v[k].y), fmaxf(v[k].z, v[k].w)));
        }
        #pragma unroll
        for (int o = 16; o; o >>= 1) m = fmaxf(m, __shfl_xor_sync(0xffffffffu, m, o));
        float s = 0.f;
        #pragma unroll
        for (int k = 0; k < 4; k++) {
            v[k].x = __expf(v[k].x - m); v[k].y = __expf(v[k].y - m);
            v[k].z = __expf(v[k].z - m); v[k].w = __expf(v[k].w - m);
            s += (v[k].x + v[k].y) + (v[k].z + v[k].w);
        }
        #pragma unroll
        for (int o = 16; o; o >>= 1) s += __shfl_xor_sync(0xffffffffu, s, o);
        const float inv = __fdividef(1.f, s);

        float4* prow = (float4*)ps[w];
        float4* arow = (float4*)(att_out + (size_t)(b * LK + l0 + w) * LQ);
        #pragma unroll
        for (int k = 0; k < 4; k++) {
            v[k].x *= inv; v[k].y *= inv; v[k].z *= inv; v[k].w *= inv;
            prow[lane + 32 * k] = v[k];          // conflict-free STS.128
            if (dsl == 0) arow[lane + 32 * k] = v[k];
        }
    }
    __syncthreads();

    // ---- context GEMM: D-half dsl, qq block w ----
    const float4* vbase = (const float4*)(value + (size_t)b * LQ * D) + dsl * 32 + lane;

    float4 acc[TL];
    #pragma unroll
    for (int l = 0; l < TL; l++) acc[l] = make_float4(0.f, 0.f, 0.f, 0.f);

    const int q0 = w * 64;
    #pragma unroll 2
    for (int qc = 0; qc < 64; qc += 4) {
        const int qq = q0 + qc;
        float4 v0 = vbase[(qq + 0) * (D / 4)];
        float4 v1 = vbase[(qq + 1) * (D / 4)];
        float4 v2 = vbase[(qq + 2) * (D / 4)];
        float4 v3 = vbase[(qq + 3) * (D / 4)];
        #pragma unroll
        for (int l = 0; l < TL; l++) {
            float4 p = *(const float4*)&ps[l][qq];   // broadcast LDS.128
            acc[l].x += p.x * v0.x; acc[l].y += p.x * v0.y;
            acc[l].z += p.x * v0.z; acc[l].w += p.x * v0.w;
            acc[l].x += p.y * v1.x; acc[l].y += p.y * v1.y;
            acc[l].z += p.y * v1.z; acc[l].w += p.y * v1.w;
            acc[l].x += p.z * v2.x; acc[l].y += p.z * v2.y;
            acc[l].z += p.z * v2.z; acc[l].w += p.z * v2.w;
            acc[l].x += p.w * v3.x; acc[l].y += p.w * v3.y;
            acc[l].z += p.w * v3.z; acc[l].w += p.w * v3.w;
        }
    }

    #pragma unroll
    for (int l = 0; l < TL; l++)
        red[w][l][lane] = acc[l];
    __syncthreads();

    // thread (lane, w) reduces 8 partials for l-row w, its d4 column
    float4 c = make_float4(0.f, 0.f, 0.f, 0.f);
    #pragma unroll
    for (int g = 0; g < TL; g++) {
        float4 r = red[g][w][lane];
        c.x += r.x; c.y += r.y; c.z += r.z; c.w += r.w;
    }
    ((float4*)ctx_out)[(size_t)(b * LK + l0 + w) * (D / 4) + dsl * 32 + lane] = c;
}

// ---------------------------------------------------------------------------
extern "C" void kernel_launch(void* const* d_in, const int* in_sizes, int n_in,
                              void* d_out, int out_size)
{
    const float* query = (const float*)d_in[0];
    const float* key   = (const float*)d_in[1];
    const float* value = (const float*)d_in[2];
    const float* Wc1   = (const float*)d_in[3];
    const float* Wc2   = (const float*)d_in[4];
    const float* vc    = (const float*)d_in[5];

    float* ctx = (float*)d_out;                 // [B, LK, D]
    float* att = ctx + (size_t)B * LK * D;      // [B, LK, LQ]

    float* sc;
    cudaGetSymbolAddress((void**)&sc, g_scores);

    proj_kernel<<<dim3(B * LQ / 16, 2), 512>>>(query, key, Wc1, Wc2);
    score_kernel<<<dim3(LQ / QBLK, LK / TL, B), NTHR>>>(vc, sc);
    context_kernel<<<dim3(2, LK / TL, B), NTHR>>>(value, sc, att, ctx);
}